// round 15
// baseline (speedup 1.0000x reference)
#include <cuda_runtime.h>
#include <math.h>

#define T_STEPS 512
#define BATCH   64
#define IDIM    256
#define CDIM    512
#define NSLOT   128
#define MDIM    64
#define GATES   2048
#define EPSV    1e-8f
#define NCTA    128
#define NTHR    1024

typedef unsigned long long ull;
typedef ulonglong2 ull2;

// ---------------- device scratch ----------------
__device__ float g_pre[(size_t)T_STEPS*BATCH*GATES];
__device__ float g_av [(size_t)T_STEPS*BATCH*MDIM];
__device__ float g_WT [3][CDIM*MDIM];     // transposed W_kw, W_kr, W_e : [k][m]
__device__ float g_WAT[IDIM*MDIM];        // transposed W_a : [k][m]
__device__ float g_h  [2][BATCH*CDIM];
__device__ float g_r  [BATCH*MDIM];
__device__ unsigned g_bar;

__device__ __forceinline__ float sigmoidf_(float x) { return 1.f/(1.f+expf(-x)); }
__device__ __forceinline__ float softplusf_(float x){ return (x > 20.f) ? x : log1pf(expf(x)); }

// ---- f32x2 helpers ----
__device__ __forceinline__ void upk(ull v, float& lo, float& hi) {
    asm("mov.b64 {%0, %1}, %2;" : "=f"(lo), "=f"(hi) : "l"(v));
}
__device__ __forceinline__ void fma2(ull& acc, ull a, ull b) {
    asm("fma.rn.f32x2 %0, %1, %2, %0;" : "+l"(acc) : "l"(a), "l"(b));
}

// ---------------- merged init (launch #0) ----------------
__global__ void __launch_bounds__(256)
init_all(const float* __restrict__ h0, const float* __restrict__ r0,
         const float* __restrict__ Wkw, const float* __restrict__ Wkr,
         const float* __restrict__ We,  const float* __restrict__ Wa) {
    int idx = blockIdx.x*256 + threadIdx.x;   // grid 128x256 = 32768
    if (idx == 0) g_bar = 0u;
    {
        int k = idx >> 6, m = idx & 63;
        g_WT[0][idx] = Wkw[m*CDIM + k];
        g_WT[1][idx] = Wkr[m*CDIM + k];
        g_WT[2][idx] = We [m*CDIM + k];
        if (idx < IDIM*MDIM)
            g_WAT[idx] = Wa[m*IDIM + k];
    }
    g_h[0][idx] = h0[idx & (CDIM-1)];
    if (idx < BATCH*MDIM)
        g_r[idx] = r0[idx & (MDIM-1)];
}

// ---------------- precompute GEMM (launch #1) ----------------
#define GP_TM 128
#define GP_TN 128
#define GP_TK 8
__global__ void __launch_bounds__(256)
gemm_pre(const float* __restrict__ A, const float* __restrict__ W,
         const float* __restrict__ bih, const float* __restrict__ bhh,
         float* __restrict__ C) {
    __shared__ float As[GP_TK][GP_TM+4];
    __shared__ float Bs[GP_TK][GP_TN+4];
    int tid  = threadIdx.x;
    int row0 = blockIdx.y * GP_TM;
    int col0 = blockIdx.x * GP_TN;
    int tx = tid & 15, ty = tid >> 4;

    ull acc2[8][4];
    #pragma unroll
    for (int i = 0; i < 8; i++)
        #pragma unroll
        for (int p = 0; p < 4; p++) acc2[i][p] = 0ull;

    float bv[8];
    #pragma unroll
    for (int j = 0; j < 8; j++) {
        int col = col0 + tx*8 + j;
        bv[j] = bih[col] + bhh[col];
    }

    for (int k0 = 0; k0 < IDIM; k0 += GP_TK) {
        int e  = tid * 4;
        int rr = e >> 3, kk = e & 7;
        float4 va = *(const float4*)&A[(size_t)(row0+rr)*IDIM + k0 + kk];
        As[kk+0][rr] = va.x; As[kk+1][rr] = va.y; As[kk+2][rr] = va.z; As[kk+3][rr] = va.w;
        float4 vb = *(const float4*)&W[(size_t)(col0+rr)*(IDIM+MDIM) + k0 + kk];
        Bs[kk+0][rr] = vb.x; Bs[kk+1][rr] = vb.y; Bs[kk+2][rr] = vb.z; Bs[kk+3][rr] = vb.w;
        __syncthreads();
        #pragma unroll
        for (int kk2 = 0; kk2 < GP_TK; kk2++) {
            float a[8];
            *(float4*)&a[0] = *(const float4*)&As[kk2][ty*8];
            *(float4*)&a[4] = *(const float4*)&As[kk2][ty*8+4];
            const float* bp = &Bs[kk2][tx*8];
            ull b2[4];
            b2[0] = *(const ull*)(bp+0);
            b2[1] = *(const ull*)(bp+2);
            b2[2] = *(const ull*)(bp+4);
            b2[3] = *(const ull*)(bp+6);
            #pragma unroll
            for (int i = 0; i < 8; i++) {
                ull ad; asm("mov.b64 %0, {%1, %1};" : "=l"(ad) : "f"(a[i]));
                #pragma unroll
                for (int p = 0; p < 4; p++) fma2(acc2[i][p], ad, b2[p]);
            }
        }
        __syncthreads();
    }
    #pragma unroll
    for (int i = 0; i < 8; i++) {
        int row = row0 + ty*8 + i;
        float c[8];
        #pragma unroll
        for (int p = 0; p < 4; p++) upk(acc2[i][p], c[2*p], c[2*p+1]);
        #pragma unroll
        for (int j = 0; j < 8; j += 4) {
            float4 v;
            v.x = c[j+0] + bv[j+0]; v.y = c[j+1] + bv[j+1];
            v.z = c[j+2] + bv[j+2]; v.w = c[j+3] + bv[j+3];
            *(float4*)&C[(size_t)row*GATES + col0 + tx*8 + j] = v;
        }
    }
}

// ---------------- precompute av (launch #2) ----------------
__global__ void __launch_bounds__(256)
pre_a_kernel(const float* __restrict__ embs, const float* __restrict__ b_a,
             float* __restrict__ ga) {
    int lane = threadIdx.x & 31, warp = threadIdx.x >> 5;
    int row = blockIdx.x*8 + warp;
    const float* er = embs + (size_t)row*IDIM;
    float acc0 = b_a[lane], acc1 = b_a[lane+32];
    #pragma unroll 8
    for (int k = 0; k < IDIM; k++) {
        float e = __ldg(&er[k]);
        acc0 = fmaf(e, g_WAT[k*64 + lane],      acc0);
        acc1 = fmaf(e, g_WAT[k*64 + lane + 32], acc1);
    }
    ga[(size_t)row*MDIM + lane]      = tanhf(acc0);
    ga[(size_t)row*MDIM + lane + 32] = tanhf(acc1);
}

// ---------------- software grid barrier ----------------
__device__ __forceinline__ void grid_bar(unsigned target) {
    __syncthreads();
    if (threadIdx.x == 0) {
        asm volatile("red.release.gpu.global.add.u32 [%0], 1;" :: "l"(&g_bar) : "memory");
        unsigned v;
        do {
            asm volatile("ld.acquire.gpu.global.u32 %0, [%1];" : "=r"(v) : "l"(&g_bar) : "memory");
        } while (v < target);
    }
    __syncthreads();
}

// ---------------- smem layout ----------------
#define SW_FLOATS   (4*4*576)      // 9216
#define SX_STRIDE   580
#define SX_FLOATS   (64*SX_STRIDE) // 37120
#define SM_STRIDE   65
#define SM_FLOATS   (NSLOT*SM_STRIDE)  // 8320
#define SPRE_FLOATS (4*4*64)       // 1024
#define RED2_OFF    8192           // aliased into sh_x: [3*256][5] = 3840 -> ends 12032
#define SMEM_TOT_BYTES ((SW_FLOATS + SX_FLOATS + SM_FLOATS + SPRE_FLOATS) * 4)

// ---------------- phase B (1024 threads) ----------------
__device__ void phase_mem(int bb, int tid, float* sh_mem, float* sb,
                          const float* __restrict__ hc,
                          const float* __restrict__ b_kr, const float* __restrict__ w_br,
                          const float* __restrict__ b_kw, const float* __restrict__ w_bw,
                          const float* __restrict__ b_e,
                          const float* __restrict__ av_t,
                          float* __restrict__ r_out, float* __restrict__ out_t) {
    float* sh_co  = sb;            // 512
    float* sh_kw  = sb + 512;
    float* sh_kr  = sb + 576;
    float* sh_e   = sb + 640;
    float* sh_a   = sb + 704;
    float* sh_wt  = sb + 768;      // 128
    float* sh_scal= sb + 1152;     // 8
    float* sh_red = sb + 1216;     // 64*17 = 1088 -> ends 2304
    float* sh_redP= sb + 2432;     // proj 3*2048=6144 -> ends 8576; addr 2048
    int lane = tid & 31, warp = tid >> 5;

    if (tid < CDIM) sh_co[tid] = __ldcg(&hc[bb*CDIM + tid]);
    if (tid < MDIM) sh_a[tid] = av_t[bb*MDIM + tid];
    __syncthreads();

    // ---- projections (512 active): thread = (kp 32, mq 16), 16 k each ----
    if (tid < 512) {
        int kp = tid >> 4, mq = (tid & 15) * 4;
        float4 aw = {0,0,0,0}, ar = {0,0,0,0}, ae = {0,0,0,0};
        const float* WTw = g_WT[0];
        const float* WTr = g_WT[1];
        const float* WTe = g_WT[2];
        int k0 = kp*16;
        #pragma unroll 4
        for (int k = k0; k < k0+16; k++) {
            float c = sh_co[k];
            float4 u = *(const float4*)&WTw[k*64 + mq];
            aw.x = fmaf(c,u.x,aw.x); aw.y = fmaf(c,u.y,aw.y);
            aw.z = fmaf(c,u.z,aw.z); aw.w = fmaf(c,u.w,aw.w);
            float4 v = *(const float4*)&WTr[k*64 + mq];
            ar.x = fmaf(c,v.x,ar.x); ar.y = fmaf(c,v.y,ar.y);
            ar.z = fmaf(c,v.z,ar.z); ar.w = fmaf(c,v.w,ar.w);
            float4 w = *(const float4*)&WTe[k*64 + mq];
            ae.x = fmaf(c,w.x,ae.x); ae.y = fmaf(c,w.y,ae.y);
            ae.z = fmaf(c,w.z,ae.z); ae.w = fmaf(c,w.w,ae.w);
        }
        *(float4*)&sh_redP[0*2048 + kp*64 + mq] = aw;
        *(float4*)&sh_redP[1*2048 + kp*64 + mq] = ar;
        *(float4*)&sh_redP[2*2048 + kp*64 + mq] = ae;
    }
    __syncthreads();
    if (tid < 192) {
        int arr = tid >> 6, m = tid & 63;
        const float* rp = &sh_redP[arr*2048 + m];
        float v = 0.f;
        #pragma unroll
        for (int u = 0; u < 32; u++) v += rp[u*64];
        if (arr == 0)      sh_kw[m] = tanhf(v + b_kw[m]);
        else if (arr == 1) sh_kr[m] = tanhf(v + b_kr[m]);
        else               sh_e[m]  = sigmoidf_(v + b_e[m]);
    }
    if (warp == 6) {
        float acc = 0.f;
        for (int k = lane; k < CDIM; k += 32) acc += sh_co[k]*w_bw[k];
        #pragma unroll
        for (int off = 16; off > 0; off >>= 1) acc += __shfl_down_sync(0xffffffffu, acc, off);
        if (lane == 0) sh_scal[0] = softplusf_(acc);
    }
    if (warp == 7) {
        float acc = 0.f;
        for (int k = lane; k < CDIM; k += 32) acc += sh_co[k]*w_br[k];
        #pragma unroll
        for (int off = 16; off > 0; off >>= 1) acc += __shfl_down_sync(0xffffffffu, acc, off);
        if (lane == 0) sh_scal[1] = softplusf_(acc);
    }
    __syncthreads();

    // ---- WRITE addressing: thread = (n 128, eighth 8), 8 m each ----
    {
        int n = tid & 127, oc = tid >> 7;
        const float* Mn = &sh_mem[n*SM_STRIDE + oc*8];
        const float* kv = &sh_kw[oc*8];
        float s = 0.f, q = 0.f;
        #pragma unroll
        for (int mm = 0; mm < 8; mm++) {
            float mv = Mn[mm];
            s = fmaf(mv, kv[mm], s);
            q = fmaf(mv, mv, q);
        }
        sh_redP[oc*128 + n]        = s;
        sh_redP[1024 + oc*128 + n] = q;
    }
    __syncthreads();
    if (tid < NSLOT) {
        float s = 0.f, q = 0.f;
        #pragma unroll
        for (int oc = 0; oc < 8; oc++) {
            s += sh_redP[oc*128 + tid];
            q += sh_redP[1024 + oc*128 + tid];
        }
        float kn = 0.f;
        #pragma unroll
        for (int m = 0; m < MDIM; m++) kn = fmaf(sh_kw[m], sh_kw[m], kn);
        sh_wt[tid] = sh_scal[0] * (s / (sqrtf(q)*sqrtf(kn) + EPSV));
    }
    __syncthreads();
    if (tid < 32) {
        float v0 = sh_wt[lane], v1 = sh_wt[lane+32], v2 = sh_wt[lane+64], v3 = sh_wt[lane+96];
        float mx = fmaxf(fmaxf(v0,v1), fmaxf(v2,v3));
        #pragma unroll
        for (int off = 16; off > 0; off >>= 1) mx = fmaxf(mx, __shfl_xor_sync(0xffffffffu, mx, off));
        float e0 = expf(v0-mx), e1 = expf(v1-mx), e2 = expf(v2-mx), e3 = expf(v3-mx);
        float ss = e0+e1+e2+e3;
        #pragma unroll
        for (int off = 16; off > 0; off >>= 1) ss += __shfl_xor_sync(0xffffffffu, ss, off);
        float inv = 1.f/ss;
        sh_wt[lane] = e0*inv; sh_wt[lane+32] = e1*inv; sh_wt[lane+64] = e2*inv; sh_wt[lane+96] = e3*inv;
    }
    __syncthreads();

    // ---- memory update (scalar; stride 1024) ----
    for (int i = tid; i < NSLOT*MDIM; i += NTHR) {
        int n = i >> 6, m = i & 63;
        float wn = sh_wt[n];
        float mv = sh_mem[n*SM_STRIDE + m];
        mv = mv*(1.f - wn*sh_e[m]) + wn*sh_a[m];
        sh_mem[n*SM_STRIDE + m] = mv;
    }
    __syncthreads();

    // ---- READ addressing ----
    {
        int n = tid & 127, oc = tid >> 7;
        const float* Mn = &sh_mem[n*SM_STRIDE + oc*8];
        const float* kv = &sh_kr[oc*8];
        float s = 0.f, q = 0.f;
        #pragma unroll
        for (int mm = 0; mm < 8; mm++) {
            float mv = Mn[mm];
            s = fmaf(mv, kv[mm], s);
            q = fmaf(mv, mv, q);
        }
        sh_redP[oc*128 + n]        = s;
        sh_redP[1024 + oc*128 + n] = q;
    }
    __syncthreads();
    if (tid < NSLOT) {
        float s = 0.f, q = 0.f;
        #pragma unroll
        for (int oc = 0; oc < 8; oc++) {
            s += sh_redP[oc*128 + tid];
            q += sh_redP[1024 + oc*128 + tid];
        }
        float kn = 0.f;
        #pragma unroll
        for (int m = 0; m < MDIM; m++) kn = fmaf(sh_kr[m], sh_kr[m], kn);
        sh_wt[tid] = sh_scal[1] * (s / (sqrtf(q)*sqrtf(kn) + EPSV));
    }
    __syncthreads();
    if (tid < 32) {
        float v0 = sh_wt[lane], v1 = sh_wt[lane+32], v2 = sh_wt[lane+64], v3 = sh_wt[lane+96];
        float mx = fmaxf(fmaxf(v0,v1), fmaxf(v2,v3));
        #pragma unroll
        for (int off = 16; off > 0; off >>= 1) mx = fmaxf(mx, __shfl_xor_sync(0xffffffffu, mx, off));
        float e0 = expf(v0-mx), e1 = expf(v1-mx), e2 = expf(v2-mx), e3 = expf(v3-mx);
        float ss = e0+e1+e2+e3;
        #pragma unroll
        for (int off = 16; off > 0; off >>= 1) ss += __shfl_xor_sync(0xffffffffu, ss, off);
        float inv = 1.f/ss;
        sh_wt[lane] = e0*inv; sh_wt[lane+32] = e1*inv; sh_wt[lane+64] = e2*inv; sh_wt[lane+96] = e3*inv;
    }
    __syncthreads();

    // ---- r = wr @ Mem : thread = (m 64, p 16), 8 n each ----
    {
        int m = tid & 63, p = tid >> 6;
        float acc = 0.f;
        int n0 = p*8;
        #pragma unroll
        for (int n = n0; n < n0+8; n++)
            acc += sh_wt[n] * sh_mem[n*SM_STRIDE + m];
        sh_red[m*17 + p] = acc;
    }
    __syncthreads();
    if (tid < MDIM) {
        const float* rr = &sh_red[tid*17];
        float rv = 0.f;
        #pragma unroll
        for (int p = 0; p < 16; p++) rv += rr[p];
        r_out[bb*MDIM + tid] = rv;
        out_t[bb*576 + 512 + tid] = rv;
    }
    __syncthreads();
}

// ---------------- persistent recurrence kernel (launch #3, 1024 thr) ----------------
__global__ void __launch_bounds__(NTHR, 1)
persist(const float* __restrict__ W_ih, const float* __restrict__ W_hh,
        const float* __restrict__ c0,   const float* __restrict__ mem0,
        const float* __restrict__ b_kr, const float* __restrict__ w_br,
        const float* __restrict__ b_kw, const float* __restrict__ w_bw,
        const float* __restrict__ b_e,
        float* __restrict__ out) {
    extern __shared__ float sm[];
    float* sh_w    = sm;                                     // [jl*4+g][576]
    float* sh_x    = sm + SW_FLOATS;                         // [64][580]
    float* sh_mem  = sm + SW_FLOATS + SX_FLOATS;             // [128][65]
    float* sh_pre  = sm + SW_FLOATS + SX_FLOATS + SM_FLOATS; // [g][jl][64]
    float* red2    = sh_x + RED2_OFF;                        // aliased; sync-guarded
    float* sb      = sh_x;                                   // phase B scratch

    int cta = blockIdx.x;
    int tid = threadIdx.x;
    int b   = tid & 63;
    int jl  = (tid >> 6) & 3;
    int kq  = tid >> 8;            // 0..3 k-quarter (144 k each)
    int j   = cta*4 + jl;

    // stage 16 gate weight rows [jl*4+g][k]
    for (int i = tid; i < SW_FLOATS; i += NTHR) {
        int k = i % 576, q = i / 576;
        int jjl = q >> 2, g = q & 3;
        int row = g*CDIM + cta*4 + jjl;
        sh_w[i] = (k < CDIM) ? W_hh[(size_t)row*CDIM + k]
                             : W_ih[(size_t)row*(IDIM+MDIM) + IDIM + (k - CDIM)];
    }
    if (cta < BATCH)
        for (int i = tid; i < NSLOT*MDIM; i += NTHR) {
            int n = i >> 6, m = i & 63;
            sh_mem[n*SM_STRIDE + m] = mem0[i];
        }
    float creg = c0[j];            // used by kq==0 threads
    __syncthreads();

    const float* xp = &sh_x[b*SX_STRIDE + kq*144];
    const float* wp = &sh_w[jl*4*576 + kq*144];

    unsigned target = 0;
    for (int t = 0; t < T_STEPS; t++) {
        int hsel = t & 1, hcur = hsel ^ 1;
        const float* hp = g_h[hsel];

        // ---- stage X = [h | r] as [b][k]; gather pre ----
        for (int i = tid; i < 8192; i += NTHR) {
            int bb = i >> 7, c4 = (i & 127)*4;
            float4 v = __ldcg((const float4*)&hp[bb*CDIM + c4]);
            *(float4*)&sh_x[bb*SX_STRIDE + c4] = v;
        }
        if (tid < 1024) {
            int i = tid;
            int bb = i >> 4, m4 = (i & 15)*4;
            float4 v = __ldcg((const float4*)&g_r[bb*MDIM + m4]);
            *(float4*)&sh_x[bb*SX_STRIDE + 512 + m4] = v;
        }
        if (tid < 256) {
            int pb = tid & 63, pg = tid >> 6;
            float4 v = *(const float4*)&g_pre[((size_t)t*BATCH + pb)*GATES + pg*512 + cta*4];
            sh_pre[pg*256 +   0 + pb] = v.x;
            sh_pre[pg*256 +  64 + pb] = v.y;
            sh_pre[pg*256 + 128 + pb] = v.z;
            sh_pre[pg*256 + 192 + pb] = v.w;
        }
        __syncthreads();

        // ---- gate GEMM: 4 acc (4 gates), 36 iters of 4k over 144 k ----
        ull A[4] = {0ull, 0ull, 0ull, 0ull};
        #pragma unroll 4
        for (int it = 0; it < 36; it++) {
            int kb = it*4;
            ull2 X = *(const ull2*)(xp + kb);
            #pragma unroll
            for (int g = 0; g < 4; g++) {
                ull2 Wv = *(const ull2*)(wp + g*576 + kb);
                fma2(A[g], X.x, Wv.x); fma2(A[g], X.y, Wv.y);
            }
        }
        float s[4];
        #pragma unroll
        for (int g = 0; g < 4; g++) {
            float lo, hi;
            upk(A[g], lo, hi); s[g] = lo + hi;
        }
        // red2 aliases X: wait for all GEMM reads before clobbering
        __syncthreads();
        if (kq != 0) {
            float* rr = &red2[((kq-1)*256 + jl*64 + b)*5];
            rr[0] = s[0]; rr[1] = s[1]; rr[2] = s[2]; rr[3] = s[3];
        }
        __syncthreads();

        float* out_t = out + (size_t)t*BATCH*(CDIM+MDIM);
        if (kq == 0) {
            #pragma unroll
            for (int u = 0; u < 3; u++) {
                const float* rr = &red2[(u*256 + jl*64 + b)*5];
                s[0] += rr[0]; s[1] += rr[1]; s[2] += rr[2]; s[3] += rr[3];
            }
            float ai = s[0] + sh_pre[0*256 + jl*64 + b];
            float af = s[1] + sh_pre[1*256 + jl*64 + b];
            float ag = s[2] + sh_pre[2*256 + jl*64 + b];
            float ao = s[3] + sh_pre[3*256 + jl*64 + b];
            float iv = sigmoidf_(ai), fv = sigmoidf_(af), ov = sigmoidf_(ao);
            float gv = tanhf(ag);
            creg = fv*creg + iv*gv;
            float hn = ov * tanhf(creg);
            g_h[hcur][b*CDIM + j] = hn;
            out_t[b*576 + j] = hn;
        }

        target += NCTA; grid_bar(target);

        if (cta < BATCH) {
            phase_mem(cta, tid, sh_mem, sb, g_h[hcur],
                      b_kr, w_br, b_kw, w_bw, b_e,
                      g_av + (size_t)t*BATCH*MDIM, g_r, out_t);
        }

        target += NCTA; grid_bar(target);
    }
}

// ---------------- launch ----------------
extern "C" void kernel_launch(void* const* d_in, const int* in_sizes, int n_in,
                              void* d_out, int out_size) {
    const float* embs = (const float*)d_in[0];
    const float* W_ih = (const float*)d_in[1];
    const float* W_hh = (const float*)d_in[2];
    const float* b_ih = (const float*)d_in[3];
    const float* b_hh = (const float*)d_in[4];
    const float* W_kr = (const float*)d_in[5];
    const float* b_kr = (const float*)d_in[6];
    const float* w_br = (const float*)d_in[7];
    const float* W_kw = (const float*)d_in[8];
    const float* b_kw = (const float*)d_in[9];
    const float* w_bw = (const float*)d_in[10];
    const float* W_e  = (const float*)d_in[11];
    const float* b_e  = (const float*)d_in[12];
    const float* W_a  = (const float*)d_in[13];
    const float* b_a  = (const float*)d_in[14];
    const float* h0   = (const float*)d_in[15];
    const float* c0   = (const float*)d_in[16];
    const float* r0   = (const float*)d_in[17];
    const float* mem0 = (const float*)d_in[18];
    float* out = (float*)d_out;

    float *p_pre, *p_av;
    cudaGetSymbolAddress((void**)&p_pre, g_pre);
    cudaGetSymbolAddress((void**)&p_av,  g_av);

    cudaFuncSetAttribute(persist, cudaFuncAttributeMaxDynamicSharedMemorySize, SMEM_TOT_BYTES);

    init_all<<<128, 256>>>(h0, r0, W_kw, W_kr, W_e, W_a);                        // 0
    gemm_pre<<<dim3(GATES/GP_TN, (T_STEPS*BATCH)/GP_TM), 256>>>(embs, W_ih, b_ih, b_hh, p_pre); // 1
    pre_a_kernel<<<(T_STEPS*BATCH)/8, 256>>>(embs, b_a, p_av);                   // 2
    persist<<<NCTA, NTHR, SMEM_TOT_BYTES>>>(W_ih, W_hh, c0, mem0,                // 3
                                            b_kr, w_br, b_kw, w_bw, b_e, out);
}

// round 16
// speedup vs baseline: 1.0845x; 1.0845x over previous
#include <cuda_runtime.h>
#include <math.h>

#define T_STEPS 512
#define BATCH   64
#define IDIM    256
#define CDIM    512
#define NSLOT   128
#define MDIM    64
#define GATES   2048
#define EPSV    1e-8f
#define NCTA    128
#define NTHR    512

typedef unsigned long long ull;
typedef ulonglong2 ull2;

// ---------------- device scratch ----------------
__device__ float g_pre[(size_t)T_STEPS*BATCH*GATES];
__device__ float g_av [(size_t)T_STEPS*BATCH*MDIM];
__device__ float g_WT [3][CDIM*MDIM];     // transposed W_kw, W_kr, W_e : [k][m]
__device__ float g_WAT[IDIM*MDIM];        // transposed W_a : [k][m]
__device__ float g_h  [2][BATCH*CDIM];
__device__ float g_r  [BATCH*MDIM];
__device__ unsigned g_bar;

__device__ __forceinline__ float sigmoidf_(float x) { return 1.f/(1.f+expf(-x)); }
__device__ __forceinline__ float softplusf_(float x){ return (x > 20.f) ? x : log1pf(expf(x)); }

// ---- f32x2 helpers ----
__device__ __forceinline__ void upk(ull v, float& lo, float& hi) {
    asm("mov.b64 {%0, %1}, %2;" : "=f"(lo), "=f"(hi) : "l"(v));
}
__device__ __forceinline__ void fma2(ull& acc, ull a, ull b) {
    asm("fma.rn.f32x2 %0, %1, %2, %0;" : "+l"(acc) : "l"(a), "l"(b));
}

// ---------------- merged init (launch #0) ----------------
__global__ void __launch_bounds__(256)
init_all(const float* __restrict__ h0, const float* __restrict__ r0,
         const float* __restrict__ Wkw, const float* __restrict__ Wkr,
         const float* __restrict__ We,  const float* __restrict__ Wa) {
    int idx = blockIdx.x*256 + threadIdx.x;   // grid 128x256 = 32768
    if (idx == 0) g_bar = 0u;
    {
        int k = idx >> 6, m = idx & 63;
        g_WT[0][idx] = Wkw[m*CDIM + k];
        g_WT[1][idx] = Wkr[m*CDIM + k];
        g_WT[2][idx] = We [m*CDIM + k];
        if (idx < IDIM*MDIM)
            g_WAT[idx] = Wa[m*IDIM + k];
    }
    g_h[0][idx] = h0[idx & (CDIM-1)];
    if (idx < BATCH*MDIM)
        g_r[idx] = r0[idx & (MDIM-1)];
}

// ---------------- precompute GEMM (launch #1) ----------------
#define GP_TM 128
#define GP_TN 128
#define GP_TK 8
__global__ void __launch_bounds__(256)
gemm_pre(const float* __restrict__ A, const float* __restrict__ W,
         const float* __restrict__ bih, const float* __restrict__ bhh,
         float* __restrict__ C) {
    __shared__ float As[GP_TK][GP_TM+4];
    __shared__ float Bs[GP_TK][GP_TN+4];
    int tid  = threadIdx.x;
    int row0 = blockIdx.y * GP_TM;
    int col0 = blockIdx.x * GP_TN;
    int tx = tid & 15, ty = tid >> 4;

    ull acc2[8][4];
    #pragma unroll
    for (int i = 0; i < 8; i++)
        #pragma unroll
        for (int p = 0; p < 4; p++) acc2[i][p] = 0ull;

    float bv[8];
    #pragma unroll
    for (int j = 0; j < 8; j++) {
        int col = col0 + tx*8 + j;
        bv[j] = bih[col] + bhh[col];
    }

    for (int k0 = 0; k0 < IDIM; k0 += GP_TK) {
        int e  = tid * 4;
        int rr = e >> 3, kk = e & 7;
        float4 va = *(const float4*)&A[(size_t)(row0+rr)*IDIM + k0 + kk];
        As[kk+0][rr] = va.x; As[kk+1][rr] = va.y; As[kk+2][rr] = va.z; As[kk+3][rr] = va.w;
        float4 vb = *(const float4*)&W[(size_t)(col0+rr)*(IDIM+MDIM) + k0 + kk];
        Bs[kk+0][rr] = vb.x; Bs[kk+1][rr] = vb.y; Bs[kk+2][rr] = vb.z; Bs[kk+3][rr] = vb.w;
        __syncthreads();
        #pragma unroll
        for (int kk2 = 0; kk2 < GP_TK; kk2++) {
            float a[8];
            *(float4*)&a[0] = *(const float4*)&As[kk2][ty*8];
            *(float4*)&a[4] = *(const float4*)&As[kk2][ty*8+4];
            const float* bp = &Bs[kk2][tx*8];
            ull b2[4];
            b2[0] = *(const ull*)(bp+0);
            b2[1] = *(const ull*)(bp+2);
            b2[2] = *(const ull*)(bp+4);
            b2[3] = *(const ull*)(bp+6);
            #pragma unroll
            for (int i = 0; i < 8; i++) {
                ull ad; asm("mov.b64 %0, {%1, %1};" : "=l"(ad) : "f"(a[i]));
                #pragma unroll
                for (int p = 0; p < 4; p++) fma2(acc2[i][p], ad, b2[p]);
            }
        }
        __syncthreads();
    }
    #pragma unroll
    for (int i = 0; i < 8; i++) {
        int row = row0 + ty*8 + i;
        float c[8];
        #pragma unroll
        for (int p = 0; p < 4; p++) upk(acc2[i][p], c[2*p], c[2*p+1]);
        #pragma unroll
        for (int j = 0; j < 8; j += 4) {
            float4 v;
            v.x = c[j+0] + bv[j+0]; v.y = c[j+1] + bv[j+1];
            v.z = c[j+2] + bv[j+2]; v.w = c[j+3] + bv[j+3];
            *(float4*)&C[(size_t)row*GATES + col0 + tx*8 + j] = v;
        }
    }
}

// ---------------- precompute av (launch #2) ----------------
__global__ void __launch_bounds__(256)
pre_a_kernel(const float* __restrict__ embs, const float* __restrict__ b_a,
             float* __restrict__ ga) {
    int lane = threadIdx.x & 31, warp = threadIdx.x >> 5;
    int row = blockIdx.x*8 + warp;
    const float* er = embs + (size_t)row*IDIM;
    float acc0 = b_a[lane], acc1 = b_a[lane+32];
    #pragma unroll 8
    for (int k = 0; k < IDIM; k++) {
        float e = __ldg(&er[k]);
        acc0 = fmaf(e, g_WAT[k*64 + lane],      acc0);
        acc1 = fmaf(e, g_WAT[k*64 + lane + 32], acc1);
    }
    ga[(size_t)row*MDIM + lane]      = tanhf(acc0);
    ga[(size_t)row*MDIM + lane + 32] = tanhf(acc1);
}

// ---------------- software grid barrier ----------------
__device__ __forceinline__ void grid_bar(unsigned target) {
    __syncthreads();
    if (threadIdx.x == 0) {
        asm volatile("red.release.gpu.global.add.u32 [%0], 1;" :: "l"(&g_bar) : "memory");
        unsigned v;
        do {
            asm volatile("ld.acquire.gpu.global.u32 %0, [%1];" : "=r"(v) : "l"(&g_bar) : "memory");
        } while (v < target);
    }
    __syncthreads();
}

// ---------------- smem layout ----------------
#define SW_FLOATS   (4*4*576)      // 9216 : [r = jl*4+g][576]
#define SX_STRIDE   580
#define SX_FLOATS   (64*SX_STRIDE) // 37120
#define SM_STRIDE   65
#define SM_FLOATS   (NSLOT*SM_STRIDE)  // 8320
#define SPRE_FLOATS (4*4*64)       // 1024
#define RED2_OFF    8192           // aliased into sh_x: [8][64][17] = 8704 -> ends 16896
#define SMEM_TOT_BYTES ((SW_FLOATS + SX_FLOATS + SM_FLOATS + SPRE_FLOATS) * 4)

// ---------------- phase B (512 threads, round-14 proven) ----------------
__device__ void phase_mem(int bb, int tid, float* sh_mem, float* sb,
                          const float* __restrict__ hc,
                          const float* __restrict__ b_kr, const float* __restrict__ w_br,
                          const float* __restrict__ b_kw, const float* __restrict__ w_bw,
                          const float* __restrict__ b_e,
                          const float* __restrict__ av_t,
                          float* __restrict__ r_out, float* __restrict__ out_t) {
    float* sh_co  = sb;            // 512
    float* sh_kw  = sb + 512;
    float* sh_kr  = sb + 576;
    float* sh_e   = sb + 640;
    float* sh_a   = sb + 704;
    float* sh_wt  = sb + 768;      // 128
    float* sh_scal= sb + 1152;     // 8
    float* sh_red = sb + 1216;     // 576 (stride 9)
    float* sh_redP= sb + 2048;     // 6144 -> ends 8192
    int lane = tid & 31, warp = tid >> 5;

    if (tid < CDIM) sh_co[tid] = __ldcg(&hc[bb*CDIM + tid]);
    if (tid < MDIM) sh_a[tid] = av_t[bb*MDIM + tid];
    __syncthreads();

    // ---- projections: thread = (kp 32, mq 16), 16 k each ----
    {
        int kp = tid >> 4, mq = (tid & 15) * 4;
        float4 aw = {0,0,0,0}, ar = {0,0,0,0}, ae = {0,0,0,0};
        const float* WTw = g_WT[0];
        const float* WTr = g_WT[1];
        const float* WTe = g_WT[2];
        int k0 = kp*16;
        #pragma unroll 4
        for (int k = k0; k < k0+16; k++) {
            float c = sh_co[k];
            float4 u = *(const float4*)&WTw[k*64 + mq];
            aw.x = fmaf(c,u.x,aw.x); aw.y = fmaf(c,u.y,aw.y);
            aw.z = fmaf(c,u.z,aw.z); aw.w = fmaf(c,u.w,aw.w);
            float4 v = *(const float4*)&WTr[k*64 + mq];
            ar.x = fmaf(c,v.x,ar.x); ar.y = fmaf(c,v.y,ar.y);
            ar.z = fmaf(c,v.z,ar.z); ar.w = fmaf(c,v.w,ar.w);
            float4 w = *(const float4*)&WTe[k*64 + mq];
            ae.x = fmaf(c,w.x,ae.x); ae.y = fmaf(c,w.y,ae.y);
            ae.z = fmaf(c,w.z,ae.z); ae.w = fmaf(c,w.w,ae.w);
        }
        *(float4*)&sh_redP[0*2048 + kp*64 + mq] = aw;
        *(float4*)&sh_redP[1*2048 + kp*64 + mq] = ar;
        *(float4*)&sh_redP[2*2048 + kp*64 + mq] = ae;
    }
    __syncthreads();
    if (tid < 192) {
        int arr = tid >> 6, m = tid & 63;
        const float* rp = &sh_redP[arr*2048 + m];
        float v = 0.f;
        #pragma unroll
        for (int u = 0; u < 32; u++) v += rp[u*64];
        if (arr == 0)      sh_kw[m] = tanhf(v + b_kw[m]);
        else if (arr == 1) sh_kr[m] = tanhf(v + b_kr[m]);
        else               sh_e[m]  = sigmoidf_(v + b_e[m]);
    }
    if (warp == 6) {
        float acc = 0.f;
        for (int k = lane; k < CDIM; k += 32) acc += sh_co[k]*w_bw[k];
        #pragma unroll
        for (int off = 16; off > 0; off >>= 1) acc += __shfl_down_sync(0xffffffffu, acc, off);
        if (lane == 0) sh_scal[0] = softplusf_(acc);
    }
    if (warp == 7) {
        float acc = 0.f;
        for (int k = lane; k < CDIM; k += 32) acc += sh_co[k]*w_br[k];
        #pragma unroll
        for (int off = 16; off > 0; off >>= 1) acc += __shfl_down_sync(0xffffffffu, acc, off);
        if (lane == 0) sh_scal[1] = softplusf_(acc);
    }
    __syncthreads();

    // ---- WRITE addressing: thread = (n 128, quarter 4), 16 m each ----
    {
        int n = tid & 127, qr = tid >> 7;
        const float* Mn = &sh_mem[n*SM_STRIDE + qr*16];
        const float* kv = &sh_kw[qr*16];
        float s = 0.f, q = 0.f;
        #pragma unroll
        for (int mm = 0; mm < 16; mm++) {
            float mv = Mn[mm];
            s = fmaf(mv, kv[mm], s);
            q = fmaf(mv, mv, q);
        }
        sh_redP[qr*128 + n]       = s;
        sh_redP[512 + qr*128 + n] = q;
    }
    __syncthreads();
    if (tid < NSLOT) {
        float s = sh_redP[tid] + sh_redP[128+tid] + sh_redP[256+tid] + sh_redP[384+tid];
        float q = sh_redP[512+tid] + sh_redP[640+tid] + sh_redP[768+tid] + sh_redP[896+tid];
        float kn = 0.f;
        #pragma unroll
        for (int m = 0; m < MDIM; m++) kn = fmaf(sh_kw[m], sh_kw[m], kn);
        sh_wt[tid] = sh_scal[0] * (s / (sqrtf(q)*sqrtf(kn) + EPSV));
    }
    __syncthreads();
    if (tid < 32) {
        float v0 = sh_wt[lane], v1 = sh_wt[lane+32], v2 = sh_wt[lane+64], v3 = sh_wt[lane+96];
        float mx = fmaxf(fmaxf(v0,v1), fmaxf(v2,v3));
        #pragma unroll
        for (int off = 16; off > 0; off >>= 1) mx = fmaxf(mx, __shfl_xor_sync(0xffffffffu, mx, off));
        float e0 = expf(v0-mx), e1 = expf(v1-mx), e2 = expf(v2-mx), e3 = expf(v3-mx);
        float ss = e0+e1+e2+e3;
        #pragma unroll
        for (int off = 16; off > 0; off >>= 1) ss += __shfl_xor_sync(0xffffffffu, ss, off);
        float inv = 1.f/ss;
        sh_wt[lane] = e0*inv; sh_wt[lane+32] = e1*inv; sh_wt[lane+64] = e2*inv; sh_wt[lane+96] = e3*inv;
    }
    __syncthreads();

    // ---- memory update (scalar; stride 512) ----
    for (int i = tid; i < NSLOT*MDIM; i += NTHR) {
        int n = i >> 6, m = i & 63;
        float wn = sh_wt[n];
        float mv = sh_mem[n*SM_STRIDE + m];
        mv = mv*(1.f - wn*sh_e[m]) + wn*sh_a[m];
        sh_mem[n*SM_STRIDE + m] = mv;
    }
    __syncthreads();

    // ---- READ addressing ----
    {
        int n = tid & 127, qr = tid >> 7;
        const float* Mn = &sh_mem[n*SM_STRIDE + qr*16];
        const float* kv = &sh_kr[qr*16];
        float s = 0.f, q = 0.f;
        #pragma unroll
        for (int mm = 0; mm < 16; mm++) {
            float mv = Mn[mm];
            s = fmaf(mv, kv[mm], s);
            q = fmaf(mv, mv, q);
        }
        sh_redP[qr*128 + n]       = s;
        sh_redP[512 + qr*128 + n] = q;
    }
    __syncthreads();
    if (tid < NSLOT) {
        float s = sh_redP[tid] + sh_redP[128+tid] + sh_redP[256+tid] + sh_redP[384+tid];
        float q = sh_redP[512+tid] + sh_redP[640+tid] + sh_redP[768+tid] + sh_redP[896+tid];
        float kn = 0.f;
        #pragma unroll
        for (int m = 0; m < MDIM; m++) kn = fmaf(sh_kr[m], sh_kr[m], kn);
        sh_wt[tid] = sh_scal[1] * (s / (sqrtf(q)*sqrtf(kn) + EPSV));
    }
    __syncthreads();
    if (tid < 32) {
        float v0 = sh_wt[lane], v1 = sh_wt[lane+32], v2 = sh_wt[lane+64], v3 = sh_wt[lane+96];
        float mx = fmaxf(fmaxf(v0,v1), fmaxf(v2,v3));
        #pragma unroll
        for (int off = 16; off > 0; off >>= 1) mx = fmaxf(mx, __shfl_xor_sync(0xffffffffu, mx, off));
        float e0 = expf(v0-mx), e1 = expf(v1-mx), e2 = expf(v2-mx), e3 = expf(v3-mx);
        float ss = e0+e1+e2+e3;
        #pragma unroll
        for (int off = 16; off > 0; off >>= 1) ss += __shfl_xor_sync(0xffffffffu, ss, off);
        float inv = 1.f/ss;
        sh_wt[lane] = e0*inv; sh_wt[lane+32] = e1*inv; sh_wt[lane+64] = e2*inv; sh_wt[lane+96] = e3*inv;
    }
    __syncthreads();

    // ---- r = wr @ Mem : thread = (m 64, p 8), 16 n each; stride-9 pad ----
    {
        int m = tid & 63, p = tid >> 6;
        float acc = 0.f;
        int n0 = p*16;
        #pragma unroll 8
        for (int n = n0; n < n0+16; n++)
            acc += sh_wt[n] * sh_mem[n*SM_STRIDE + m];
        sh_red[m*9 + p] = acc;
    }
    __syncthreads();
    if (tid < MDIM) {
        const float* rr = &sh_red[tid*9];
        float rv = rr[0]+rr[1]+rr[2]+rr[3]+rr[4]+rr[5]+rr[6]+rr[7];
        r_out[bb*MDIM + tid] = rv;
        out_t[bb*576 + 512 + tid] = rv;
    }
    __syncthreads();
}

// ---------------- persistent recurrence kernel (launch #3, 512 thr) ----------------
__global__ void __launch_bounds__(NTHR, 1)
persist(const float* __restrict__ W_ih, const float* __restrict__ W_hh,
        const float* __restrict__ c0,   const float* __restrict__ mem0,
        const float* __restrict__ b_kr, const float* __restrict__ w_br,
        const float* __restrict__ b_kw, const float* __restrict__ w_bw,
        const float* __restrict__ b_e,
        float* __restrict__ out) {
    extern __shared__ float sm[];
    float* sh_w    = sm;                                     // [r = jl*4+g][576]
    float* sh_x    = sm + SW_FLOATS;                         // [64][580]
    float* sh_mem  = sm + SW_FLOATS + SX_FLOATS;             // [128][65]
    float* sh_pre  = sm + SW_FLOATS + SX_FLOATS + SM_FLOATS; // [g][jl][64]
    float* red2    = sh_x + RED2_OFF;                        // [8][64][17] aliased; sync-guarded
    float* sb      = sh_x;                                   // phase B scratch

    int cta = blockIdx.x;
    int tid = threadIdx.x;
    int b   = tid & 63;            // GEMM batch
    int kh  = tid >> 6;            // 0..7 k-eighth (72 k each)
    int fb  = tid & 63;            // finalize batch (tid<256)
    int fjl = (tid >> 6) & 3;      // finalize j-local

    // stage 16 gate weight rows [r = jl*4+g][k]
    for (int i = tid; i < SW_FLOATS; i += NTHR) {
        int k = i % 576, q = i / 576;
        int jjl = q >> 2, g = q & 3;
        int row = g*CDIM + cta*4 + jjl;
        sh_w[i] = (k < CDIM) ? W_hh[(size_t)row*CDIM + k]
                             : W_ih[(size_t)row*(IDIM+MDIM) + IDIM + (k - CDIM)];
    }
    if (cta < BATCH)
        for (int i = tid; i < NSLOT*MDIM; i += NTHR) {
            int n = i >> 6, m = i & 63;
            sh_mem[n*SM_STRIDE + m] = mem0[i];
        }
    float creg = c0[cta*4 + fjl];  // used by tid<256 threads
    __syncthreads();

    const float* xp = &sh_x[b*SX_STRIDE + kh*72];
    const float* wp = &sh_w[kh*72];

    unsigned target = 0;
    for (int t = 0; t < T_STEPS; t++) {
        int hsel = t & 1, hcur = hsel ^ 1;
        const float* hp = g_h[hsel];

        // ---- stage X = [h | r] as [b][k]; gather pre ----
        for (int i = tid; i < 8192; i += NTHR) {
            int bb = i >> 7, c4 = (i & 127)*4;
            float4 v = __ldcg((const float4*)&hp[bb*CDIM + c4]);
            *(float4*)&sh_x[bb*SX_STRIDE + c4] = v;
        }
        for (int i = tid; i < 1024; i += NTHR) {
            int bb = i >> 4, m4 = (i & 15)*4;
            float4 v = __ldcg((const float4*)&g_r[bb*MDIM + m4]);
            *(float4*)&sh_x[bb*SX_STRIDE + 512 + m4] = v;
        }
        if (tid < 256) {
            int pb = tid & 63, pg = tid >> 6;
            float4 v = *(const float4*)&g_pre[((size_t)t*BATCH + pb)*GATES + pg*512 + cta*4];
            sh_pre[pg*256 +   0 + pb] = v.x;
            sh_pre[pg*256 +  64 + pb] = v.y;
            sh_pre[pg*256 + 128 + pb] = v.z;
            sh_pre[pg*256 + 192 + pb] = v.w;
        }
        __syncthreads();

        // ---- gate GEMM: thread = (b, kh); ALL 16 gate rows; X loaded once ----
        ull A[16];
        #pragma unroll
        for (int r = 0; r < 16; r++) A[r] = 0ull;
        #pragma unroll 3
        for (int it = 0; it < 18; it++) {
            int kb = it*4;
            ull2 X = *(const ull2*)(xp + kb);
            #pragma unroll
            for (int r = 0; r < 16; r++) {
                ull2 Wv = *(const ull2*)(wp + r*576 + kb);
                fma2(A[r], X.x, Wv.x); fma2(A[r], X.y, Wv.y);
            }
        }
        float s[16];
        #pragma unroll
        for (int r = 0; r < 16; r++) {
            float lo, hi;
            upk(A[r], lo, hi); s[r] = lo + hi;
        }
        // red2 aliases X: wait for all GEMM reads before clobbering
        __syncthreads();
        {
            float* rr = &red2[(kh*64 + b)*17];
            #pragma unroll
            for (int r = 0; r < 16; r++) rr[r] = s[r];
        }
        __syncthreads();

        float* out_t = out + (size_t)t*BATCH*(CDIM+MDIM);
        if (tid < 256) {
            // finalize: thread = (fb, fjl) sums 4 gates over 8 kh partials
            float sg[4] = {0.f, 0.f, 0.f, 0.f};
            #pragma unroll
            for (int k2 = 0; k2 < 8; k2++) {
                const float* rr = &red2[(k2*64 + fb)*17 + fjl*4];
                sg[0] += rr[0]; sg[1] += rr[1]; sg[2] += rr[2]; sg[3] += rr[3];
            }
            int j = cta*4 + fjl;
            float ai = sg[0] + sh_pre[0*256 + fjl*64 + fb];
            float af = sg[1] + sh_pre[1*256 + fjl*64 + fb];
            float ag = sg[2] + sh_pre[2*256 + fjl*64 + fb];
            float ao = sg[3] + sh_pre[3*256 + fjl*64 + fb];
            float iv = sigmoidf_(ai), fv = sigmoidf_(af), ov = sigmoidf_(ao);
            float gv = tanhf(ag);
            creg = fv*creg + iv*gv;
            float hn = ov * tanhf(creg);
            g_h[hcur][fb*CDIM + j] = hn;
            out_t[fb*576 + j] = hn;
        }

        target += NCTA; grid_bar(target);

        if (cta < BATCH) {
            phase_mem(cta, tid, sh_mem, sb, g_h[hcur],
                      b_kr, w_br, b_kw, w_bw, b_e,
                      g_av + (size_t)t*BATCH*MDIM, g_r, out_t);
        }

        target += NCTA; grid_bar(target);
    }
}

// ---------------- launch ----------------
extern "C" void kernel_launch(void* const* d_in, const int* in_sizes, int n_in,
                              void* d_out, int out_size) {
    const float* embs = (const float*)d_in[0];
    const float* W_ih = (const float*)d_in[1];
    const float* W_hh = (const float*)d_in[2];
    const float* b_ih = (const float*)d_in[3];
    const float* b_hh = (const float*)d_in[4];
    const float* W_kr = (const float*)d_in[5];
    const float* b_kr = (const float*)d_in[6];
    const float* w_br = (const float*)d_in[7];
    const float* W_kw = (const float*)d_in[8];
    const float* b_kw = (const float*)d_in[9];
    const float* w_bw = (const float*)d_in[10];
    const float* W_e  = (const float*)d_in[11];
    const float* b_e  = (const float*)d_in[12];
    const float* W_a  = (const float*)d_in[13];
    const float* b_a  = (const float*)d_in[14];
    const float* h0   = (const float*)d_in[15];
    const float* c0   = (const float*)d_in[16];
    const float* r0   = (const float*)d_in[17];
    const float* mem0 = (const float*)d_in[18];
    float* out = (float*)d_out;

    float *p_pre, *p_av;
    cudaGetSymbolAddress((void**)&p_pre, g_pre);
    cudaGetSymbolAddress((void**)&p_av,  g_av);

    cudaFuncSetAttribute(persist, cudaFuncAttributeMaxDynamicSharedMemorySize, SMEM_TOT_BYTES);

    init_all<<<128, 256>>>(h0, r0, W_kw, W_kr, W_e, W_a);                        // 0
    gemm_pre<<<dim3(GATES/GP_TN, (T_STEPS*BATCH)/GP_TM), 256>>>(embs, W_ih, b_ih, b_hh, p_pre); // 1
    pre_a_kernel<<<(T_STEPS*BATCH)/8, 256>>>(embs, b_a, p_av);                   // 2
    persist<<<NCTA, NTHR, SMEM_TOT_BYTES>>>(W_ih, W_hh, c0, mem0,                // 3
                                            b_kr, w_br, b_kw, w_bw, b_e, out);
}

// round 17
// speedup vs baseline: 1.1269x; 1.0391x over previous
#include <cuda_runtime.h>
#include <math.h>

#define T_STEPS 512
#define BATCH   64
#define IDIM    256
#define CDIM    512
#define NSLOT   128
#define MDIM    64
#define GATES   2048
#define EPSV    1e-8f
#define NCTA    128
#define NTHR    512

typedef unsigned long long ull;
typedef ulonglong2 ull2;

// ---------------- device scratch ----------------
__device__ float g_pre[(size_t)T_STEPS*BATCH*GATES];
__device__ float g_av [(size_t)T_STEPS*BATCH*MDIM];
__device__ float g_WT [3][CDIM*MDIM];     // transposed W_kw, W_kr, W_e : [k][m]
__device__ float g_WAT[IDIM*MDIM];        // transposed W_a : [k][m]
__device__ float g_h  [2][BATCH*CDIM];
__device__ float g_r  [BATCH*MDIM];
__device__ unsigned g_bar;

__device__ __forceinline__ float sigmoidf_(float x) { return 1.f/(1.f+expf(-x)); }
__device__ __forceinline__ float softplusf_(float x){ return (x > 20.f) ? x : log1pf(expf(x)); }

// ---- f32x2 helpers ----
__device__ __forceinline__ void upk(ull v, float& lo, float& hi) {
    asm("mov.b64 {%0, %1}, %2;" : "=f"(lo), "=f"(hi) : "l"(v));
}
__device__ __forceinline__ void fma2(ull& acc, ull a, ull b) {
    asm("fma.rn.f32x2 %0, %1, %2, %0;" : "+l"(acc) : "l"(a), "l"(b));
}

// ---------------- merged init (launch #0) ----------------
__global__ void __launch_bounds__(256)
init_all(const float* __restrict__ h0, const float* __restrict__ r0,
         const float* __restrict__ Wkw, const float* __restrict__ Wkr,
         const float* __restrict__ We,  const float* __restrict__ Wa) {
    int idx = blockIdx.x*256 + threadIdx.x;   // grid 128x256 = 32768
    if (idx == 0) g_bar = 0u;
    {
        int k = idx >> 6, m = idx & 63;
        g_WT[0][idx] = Wkw[m*CDIM + k];
        g_WT[1][idx] = Wkr[m*CDIM + k];
        g_WT[2][idx] = We [m*CDIM + k];
        if (idx < IDIM*MDIM)
            g_WAT[idx] = Wa[m*IDIM + k];
    }
    g_h[0][idx] = h0[idx & (CDIM-1)];
    if (idx < BATCH*MDIM)
        g_r[idx] = r0[idx & (MDIM-1)];
}

// ---------------- precompute GEMM (launch #1) ----------------
#define GP_TM 128
#define GP_TN 128
#define GP_TK 8
__global__ void __launch_bounds__(256)
gemm_pre(const float* __restrict__ A, const float* __restrict__ W,
         const float* __restrict__ bih, const float* __restrict__ bhh,
         float* __restrict__ C) {
    __shared__ float As[GP_TK][GP_TM+4];
    __shared__ float Bs[GP_TK][GP_TN+4];
    int tid  = threadIdx.x;
    int row0 = blockIdx.y * GP_TM;
    int col0 = blockIdx.x * GP_TN;
    int tx = tid & 15, ty = tid >> 4;

    ull acc2[8][4];
    #pragma unroll
    for (int i = 0; i < 8; i++)
        #pragma unroll
        for (int p = 0; p < 4; p++) acc2[i][p] = 0ull;

    float bv[8];
    #pragma unroll
    for (int j = 0; j < 8; j++) {
        int col = col0 + tx*8 + j;
        bv[j] = bih[col] + bhh[col];
    }

    for (int k0 = 0; k0 < IDIM; k0 += GP_TK) {
        int e  = tid * 4;
        int rr = e >> 3, kk = e & 7;
        float4 va = *(const float4*)&A[(size_t)(row0+rr)*IDIM + k0 + kk];
        As[kk+0][rr] = va.x; As[kk+1][rr] = va.y; As[kk+2][rr] = va.z; As[kk+3][rr] = va.w;
        float4 vb = *(const float4*)&W[(size_t)(col0+rr)*(IDIM+MDIM) + k0 + kk];
        Bs[kk+0][rr] = vb.x; Bs[kk+1][rr] = vb.y; Bs[kk+2][rr] = vb.z; Bs[kk+3][rr] = vb.w;
        __syncthreads();
        #pragma unroll
        for (int kk2 = 0; kk2 < GP_TK; kk2++) {
            float a[8];
            *(float4*)&a[0] = *(const float4*)&As[kk2][ty*8];
            *(float4*)&a[4] = *(const float4*)&As[kk2][ty*8+4];
            const float* bp = &Bs[kk2][tx*8];
            ull b2[4];
            b2[0] = *(const ull*)(bp+0);
            b2[1] = *(const ull*)(bp+2);
            b2[2] = *(const ull*)(bp+4);
            b2[3] = *(const ull*)(bp+6);
            #pragma unroll
            for (int i = 0; i < 8; i++) {
                ull ad; asm("mov.b64 %0, {%1, %1};" : "=l"(ad) : "f"(a[i]));
                #pragma unroll
                for (int p = 0; p < 4; p++) fma2(acc2[i][p], ad, b2[p]);
            }
        }
        __syncthreads();
    }
    #pragma unroll
    for (int i = 0; i < 8; i++) {
        int row = row0 + ty*8 + i;
        float c[8];
        #pragma unroll
        for (int p = 0; p < 4; p++) upk(acc2[i][p], c[2*p], c[2*p+1]);
        #pragma unroll
        for (int j = 0; j < 8; j += 4) {
            float4 v;
            v.x = c[j+0] + bv[j+0]; v.y = c[j+1] + bv[j+1];
            v.z = c[j+2] + bv[j+2]; v.w = c[j+3] + bv[j+3];
            *(float4*)&C[(size_t)row*GATES + col0 + tx*8 + j] = v;
        }
    }
}

// ---------------- precompute av (launch #2) ----------------
__global__ void __launch_bounds__(256)
pre_a_kernel(const float* __restrict__ embs, const float* __restrict__ b_a,
             float* __restrict__ ga) {
    int lane = threadIdx.x & 31, warp = threadIdx.x >> 5;
    int row = blockIdx.x*8 + warp;
    const float* er = embs + (size_t)row*IDIM;
    float acc0 = b_a[lane], acc1 = b_a[lane+32];
    #pragma unroll 8
    for (int k = 0; k < IDIM; k++) {
        float e = __ldg(&er[k]);
        acc0 = fmaf(e, g_WAT[k*64 + lane],      acc0);
        acc1 = fmaf(e, g_WAT[k*64 + lane + 32], acc1);
    }
    ga[(size_t)row*MDIM + lane]      = tanhf(acc0);
    ga[(size_t)row*MDIM + lane + 32] = tanhf(acc1);
}

// ---------------- software grid barrier ----------------
__device__ __forceinline__ void grid_bar(unsigned target) {
    __syncthreads();
    if (threadIdx.x == 0) {
        asm volatile("red.release.gpu.global.add.u32 [%0], 1;" :: "l"(&g_bar) : "memory");
        unsigned v;
        do {
            asm volatile("ld.acquire.gpu.global.u32 %0, [%1];" : "=r"(v) : "l"(&g_bar) : "memory");
        } while (v < target);
    }
    __syncthreads();
}

// ---------------- smem layout ----------------
#define SW_FLOATS   (4*4*576)      // 9216
#define SX_STRIDE   580
#define SX_FLOATS   (64*SX_STRIDE) // 37120
#define SM_STRIDE   65
#define SM_FLOATS   (NSLOT*SM_STRIDE)  // 8320
#define SPRE_FLOATS (4*4*64)       // 1024
#define RED2_OFF    8192           // aliased into sh_x; [7*64][17] = 7616 -> ends 15808
#define SMEM_TOT_BYTES ((SW_FLOATS + SX_FLOATS + SM_FLOATS + SPRE_FLOATS) * 4)

// ---------------- phase B (512 threads) ----------------
__device__ void phase_mem(int bb, int tid, float* sh_mem, float* sb,
                          const float* __restrict__ hc,
                          const float* __restrict__ b_kr, const float* __restrict__ w_br,
                          const float* __restrict__ b_kw, const float* __restrict__ w_bw,
                          const float* __restrict__ b_e,
                          const float* __restrict__ av_t,
                          float* __restrict__ r_out, float* __restrict__ out_t) {
    float* sh_co  = sb;            // 512
    float* sh_kw  = sb + 512;
    float* sh_kr  = sb + 576;
    float* sh_e   = sb + 640;
    float* sh_a   = sb + 704;
    float* sh_wt  = sb + 768;      // 128
    float* sh_scal= sb + 1152;     // 8
    float* sh_red = sb + 1216;     // 576 (stride 9)
    float* sh_redP= sb + 2048;     // 6144 -> ends 8192
    int lane = tid & 31, warp = tid >> 5;

    if (tid < CDIM) sh_co[tid] = __ldcg(&hc[bb*CDIM + tid]);
    if (tid < MDIM) sh_a[tid] = av_t[bb*MDIM + tid];
    __syncthreads();

    // ---- projections: thread = (kp 32, mq 16), 16 k each ----
    {
        int kp = tid >> 4, mq = (tid & 15) * 4;
        float4 aw = {0,0,0,0}, ar = {0,0,0,0}, ae = {0,0,0,0};
        const float* WTw = g_WT[0];
        const float* WTr = g_WT[1];
        const float* WTe = g_WT[2];
        int k0 = kp*16;
        #pragma unroll 4
        for (int k = k0; k < k0+16; k++) {
            float c = sh_co[k];
            float4 u = *(const float4*)&WTw[k*64 + mq];
            aw.x = fmaf(c,u.x,aw.x); aw.y = fmaf(c,u.y,aw.y);
            aw.z = fmaf(c,u.z,aw.z); aw.w = fmaf(c,u.w,aw.w);
            float4 v = *(const float4*)&WTr[k*64 + mq];
            ar.x = fmaf(c,v.x,ar.x); ar.y = fmaf(c,v.y,ar.y);
            ar.z = fmaf(c,v.z,ar.z); ar.w = fmaf(c,v.w,ar.w);
            float4 w = *(const float4*)&WTe[k*64 + mq];
            ae.x = fmaf(c,w.x,ae.x); ae.y = fmaf(c,w.y,ae.y);
            ae.z = fmaf(c,w.z,ae.z); ae.w = fmaf(c,w.w,ae.w);
        }
        *(float4*)&sh_redP[0*2048 + kp*64 + mq] = aw;
        *(float4*)&sh_redP[1*2048 + kp*64 + mq] = ar;
        *(float4*)&sh_redP[2*2048 + kp*64 + mq] = ae;
    }
    __syncthreads();
    if (tid < 192) {
        int arr = tid >> 6, m = tid & 63;
        const float* rp = &sh_redP[arr*2048 + m];
        float v = 0.f;
        #pragma unroll
        for (int u = 0; u < 32; u++) v += rp[u*64];
        if (arr == 0)      sh_kw[m] = tanhf(v + b_kw[m]);
        else if (arr == 1) sh_kr[m] = tanhf(v + b_kr[m]);
        else               sh_e[m]  = sigmoidf_(v + b_e[m]);
    }
    if (warp == 6) {
        float acc = 0.f;
        for (int k = lane; k < CDIM; k += 32) acc += sh_co[k]*w_bw[k];
        #pragma unroll
        for (int off = 16; off > 0; off >>= 1) acc += __shfl_down_sync(0xffffffffu, acc, off);
        if (lane == 0) sh_scal[0] = softplusf_(acc);
    }
    if (warp == 7) {
        float acc = 0.f;
        for (int k = lane; k < CDIM; k += 32) acc += sh_co[k]*w_br[k];
        #pragma unroll
        for (int off = 16; off > 0; off >>= 1) acc += __shfl_down_sync(0xffffffffu, acc, off);
        if (lane == 0) sh_scal[1] = softplusf_(acc);
    }
    __syncthreads();

    // ---- WRITE addressing: thread = (n 128, quarter 4), 16 m each ----
    {
        int n = tid & 127, qr = tid >> 7;
        const float* Mn = &sh_mem[n*SM_STRIDE + qr*16];
        const float* kv = &sh_kw[qr*16];
        float s = 0.f, q = 0.f;
        #pragma unroll
        for (int mm = 0; mm < 16; mm++) {
            float mv = Mn[mm];
            s = fmaf(mv, kv[mm], s);
            q = fmaf(mv, mv, q);
        }
        sh_redP[qr*128 + n]       = s;
        sh_redP[512 + qr*128 + n] = q;
    }
    __syncthreads();
    if (tid < NSLOT) {
        float s = sh_redP[tid] + sh_redP[128+tid] + sh_redP[256+tid] + sh_redP[384+tid];
        float q = sh_redP[512+tid] + sh_redP[640+tid] + sh_redP[768+tid] + sh_redP[896+tid];
        float kn = 0.f;
        #pragma unroll
        for (int m = 0; m < MDIM; m++) kn = fmaf(sh_kw[m], sh_kw[m], kn);
        sh_wt[tid] = sh_scal[0] * (s / (sqrtf(q)*sqrtf(kn) + EPSV));
    }
    __syncthreads();
    if (tid < 32) {
        float v0 = sh_wt[lane], v1 = sh_wt[lane+32], v2 = sh_wt[lane+64], v3 = sh_wt[lane+96];
        float mx = fmaxf(fmaxf(v0,v1), fmaxf(v2,v3));
        #pragma unroll
        for (int off = 16; off > 0; off >>= 1) mx = fmaxf(mx, __shfl_xor_sync(0xffffffffu, mx, off));
        float e0 = expf(v0-mx), e1 = expf(v1-mx), e2 = expf(v2-mx), e3 = expf(v3-mx);
        float ss = e0+e1+e2+e3;
        #pragma unroll
        for (int off = 16; off > 0; off >>= 1) ss += __shfl_xor_sync(0xffffffffu, ss, off);
        float inv = 1.f/ss;
        sh_wt[lane] = e0*inv; sh_wt[lane+32] = e1*inv; sh_wt[lane+64] = e2*inv; sh_wt[lane+96] = e3*inv;
    }
    __syncthreads();

    // ---- memory update (scalar; stride 512) ----
    for (int i = tid; i < NSLOT*MDIM; i += NTHR) {
        int n = i >> 6, m = i & 63;
        float wn = sh_wt[n];
        float mv = sh_mem[n*SM_STRIDE + m];
        mv = mv*(1.f - wn*sh_e[m]) + wn*sh_a[m];
        sh_mem[n*SM_STRIDE + m] = mv;
    }
    __syncthreads();

    // ---- READ addressing ----
    {
        int n = tid & 127, qr = tid >> 7;
        const float* Mn = &sh_mem[n*SM_STRIDE + qr*16];
        const float* kv = &sh_kr[qr*16];
        float s = 0.f, q = 0.f;
        #pragma unroll
        for (int mm = 0; mm < 16; mm++) {
            float mv = Mn[mm];
            s = fmaf(mv, kv[mm], s);
            q = fmaf(mv, mv, q);
        }
        sh_redP[qr*128 + n]       = s;
        sh_redP[512 + qr*128 + n] = q;
    }
    __syncthreads();
    if (tid < NSLOT) {
        float s = sh_redP[tid] + sh_redP[128+tid] + sh_redP[256+tid] + sh_redP[384+tid];
        float q = sh_redP[512+tid] + sh_redP[640+tid] + sh_redP[768+tid] + sh_redP[896+tid];
        float kn = 0.f;
        #pragma unroll
        for (int m = 0; m < MDIM; m++) kn = fmaf(sh_kr[m], sh_kr[m], kn);
        sh_wt[tid] = sh_scal[1] * (s / (sqrtf(q)*sqrtf(kn) + EPSV));
    }
    __syncthreads();
    if (tid < 32) {
        float v0 = sh_wt[lane], v1 = sh_wt[lane+32], v2 = sh_wt[lane+64], v3 = sh_wt[lane+96];
        float mx = fmaxf(fmaxf(v0,v1), fmaxf(v2,v3));
        #pragma unroll
        for (int off = 16; off > 0; off >>= 1) mx = fmaxf(mx, __shfl_xor_sync(0xffffffffu, mx, off));
        float e0 = expf(v0-mx), e1 = expf(v1-mx), e2 = expf(v2-mx), e3 = expf(v3-mx);
        float ss = e0+e1+e2+e3;
        #pragma unroll
        for (int off = 16; off > 0; off >>= 1) ss += __shfl_xor_sync(0xffffffffu, ss, off);
        float inv = 1.f/ss;
        sh_wt[lane] = e0*inv; sh_wt[lane+32] = e1*inv; sh_wt[lane+64] = e2*inv; sh_wt[lane+96] = e3*inv;
    }
    __syncthreads();

    // ---- r = wr @ Mem : thread = (m 64, p 8), 16 n each; stride-9 pad ----
    {
        int m = tid & 63, p = tid >> 6;
        float acc = 0.f;
        int n0 = p*16;
        #pragma unroll 8
        for (int n = n0; n < n0+16; n++)
            acc += sh_wt[n] * sh_mem[n*SM_STRIDE + m];
        sh_red[m*9 + p] = acc;
    }
    __syncthreads();
    if (tid < MDIM) {
        const float* rr = &sh_red[tid*9];
        float rv = rr[0]+rr[1]+rr[2]+rr[3]+rr[4]+rr[5]+rr[6]+rr[7];
        r_out[bb*MDIM + tid] = rv;
        out_t[bb*576 + 512 + tid] = rv;
    }
    __syncthreads();
}

// ---------------- persistent recurrence kernel (launch #3, 512 thr) ----------------
__global__ void __launch_bounds__(NTHR, 1)
persist(const float* __restrict__ W_ih, const float* __restrict__ W_hh,
        const float* __restrict__ c0,   const float* __restrict__ mem0,
        const float* __restrict__ b_kr, const float* __restrict__ w_br,
        const float* __restrict__ b_kw, const float* __restrict__ w_bw,
        const float* __restrict__ b_e,
        float* __restrict__ out) {
    extern __shared__ float sm[];
    float* sh_w    = sm;                                     // [jl*4+g][576]
    float* sh_x    = sm + SW_FLOATS;                         // [64][580]
    float* sh_mem  = sm + SW_FLOATS + SX_FLOATS;             // [128][65]
    float* sh_pre  = sm + SW_FLOATS + SX_FLOATS + SM_FLOATS; // [g][jl][64]
    float* red2    = sh_x + RED2_OFF;                        // aliased; sync-guarded
    float* sb      = sh_x;                                   // phase B scratch

    int cta = blockIdx.x;
    int tid = threadIdx.x;
    int bp  = tid & 31;
    int jp  = (tid >> 5) & 1;
    int kh  = tid >> 6;            // 0..7 k-eighth
    int b0  = bp, b1 = bp + 32;
    int j0  = cta*4 + jp*2;

    // stage 16 gate weight rows [jl*4+g][k]
    for (int i = tid; i < SW_FLOATS; i += NTHR) {
        int k = i % 576, q = i / 576;
        int jl = q >> 2, g = q & 3;
        int row = g*CDIM + cta*4 + jl;
        sh_w[i] = (k < CDIM) ? W_hh[(size_t)row*CDIM + k]
                             : W_ih[(size_t)row*(IDIM+MDIM) + IDIM + (k - CDIM)];
    }
    if (cta < BATCH)
        for (int i = tid; i < NSLOT*MDIM; i += NTHR) {
            int n = i >> 6, m = i & 63;
            sh_mem[n*SM_STRIDE + m] = mem0[i];
        }
    float c00 = c0[j0], c01 = c0[j0+1];
    float c10 = c00,    c11 = c01;
    __syncthreads();

    const float* xp0 = &sh_x[b0*SX_STRIDE + kh*72];
    const float* xp1 = &sh_x[b1*SX_STRIDE + kh*72];
    const float* wp  = &sh_w[jp*4608 + kh*72];

    unsigned target = 0;
    for (int t = 0; t < T_STEPS; t++) {
        int hsel = t & 1, hcur = hsel ^ 1;
        const float* hp = g_h[hsel];

        // ---- stage X = [h | r] as [b][k]; gather pre (GUARDED: tid<256 only) ----
        for (int i = tid; i < 8192; i += NTHR) {
            int bb = i >> 7, c4 = (i & 127)*4;
            float4 v = __ldcg((const float4*)&hp[bb*CDIM + c4]);
            *(float4*)&sh_x[bb*SX_STRIDE + c4] = v;
        }
        for (int i = tid; i < 1024; i += NTHR) {
            int bb = i >> 4, m4 = (i & 15)*4;
            float4 v = __ldcg((const float4*)&g_r[bb*MDIM + m4]);
            *(float4*)&sh_x[bb*SX_STRIDE + 512 + m4] = v;
        }
        if (tid < 256) {
            int pb = tid & 63, pg = tid >> 6;
            float4 v = *(const float4*)&g_pre[((size_t)t*BATCH + pb)*GATES + pg*512 + cta*4];
            sh_pre[pg*256 +   0 + pb] = v.x;
            sh_pre[pg*256 +  64 + pb] = v.y;
            sh_pre[pg*256 + 128 + pb] = v.z;
            sh_pre[pg*256 + 192 + pb] = v.w;
        }
        __syncthreads();

        // ---- gate GEMM: 16 acc (2b x 2j x 4g), 18 iters of 4k ----
        ull A0[8], A1[8];
        #pragma unroll
        for (int q = 0; q < 8; q++) { A0[q] = 0ull; A1[q] = 0ull; }
        #pragma unroll 2
        for (int it = 0; it < 18; it++) {
            int kb = it*4;
            ull2 X0 = *(const ull2*)(xp0 + kb);
            ull2 X1 = *(const ull2*)(xp1 + kb);
            #pragma unroll
            for (int q = 0; q < 8; q++) {
                ull2 Wv = *(const ull2*)(wp + q*576 + kb);
                fma2(A0[q], X0.x, Wv.x); fma2(A0[q], X0.y, Wv.y);
                fma2(A1[q], X1.x, Wv.x); fma2(A1[q], X1.y, Wv.y);
            }
        }
        float s0[8], s1[8];
        #pragma unroll
        for (int q = 0; q < 8; q++) {
            float lo, hi;
            upk(A0[q], lo, hi); s0[q] = lo + hi;
            upk(A1[q], lo, hi); s1[q] = lo + hi;
        }
        // red2 aliases X: wait for all GEMM reads before clobbering
        __syncthreads();
        if (kh != 0) {
            float* rr = &red2[((kh-1)*64 + jp*32 + bp)*17];
            #pragma unroll
            for (int q = 0; q < 8; q++) { rr[q] = s0[q]; rr[8+q] = s1[q]; }
        }
        __syncthreads();

        float* out_t = out + (size_t)t*BATCH*(CDIM+MDIM);
        if (kh == 0) {
            #pragma unroll
            for (int u = 0; u < 7; u++) {
                const float* rr = &red2[(u*64 + jp*32 + bp)*17];
                #pragma unroll
                for (int q = 0; q < 8; q++) { s0[q] += rr[q]; s1[q] += rr[8+q]; }
            }
            #pragma unroll
            for (int bi = 0; bi < 2; bi++) {
                int b = (bi == 0) ? b0 : b1;
                const float* sv = (bi == 0) ? s0 : s1;
                #pragma unroll
                for (int jx = 0; jx < 2; jx++) {
                    int jl = jp*2 + jx;
                    int j  = cta*4 + jl;
                    float ai = sv[jx*4+0] + sh_pre[0*256 + jl*64 + b];
                    float af = sv[jx*4+1] + sh_pre[1*256 + jl*64 + b];
                    float ag = sv[jx*4+2] + sh_pre[2*256 + jl*64 + b];
                    float ao = sv[jx*4+3] + sh_pre[3*256 + jl*64 + b];
                    float iv = sigmoidf_(ai), fv = sigmoidf_(af), ov = sigmoidf_(ao);
                    float gv = tanhf(ag);
                    float cr;
                    if (bi == 0) cr = (jx == 0) ? c00 : c01;
                    else         cr = (jx == 0) ? c10 : c11;
                    cr = fv*cr + iv*gv;
                    if (bi == 0) { if (jx == 0) c00 = cr; else c01 = cr; }
                    else         { if (jx == 0) c10 = cr; else c11 = cr; }
                    float hn = ov * tanhf(cr);
                    g_h[hcur][b*CDIM + j] = hn;
                    out_t[b*576 + j] = hn;
                }
            }
        }

        target += NCTA; grid_bar(target);

        if (cta < BATCH) {
            phase_mem(cta, tid, sh_mem, sb, g_h[hcur],
                      b_kr, w_br, b_kw, w_bw, b_e,
                      g_av + (size_t)t*BATCH*MDIM, g_r, out_t);
        }

        target += NCTA; grid_bar(target);
    }
}

// ---------------- launch ----------------
extern "C" void kernel_launch(void* const* d_in, const int* in_sizes, int n_in,
                              void* d_out, int out_size) {
    const float* embs = (const float*)d_in[0];
    const float* W_ih = (const float*)d_in[1];
    const float* W_hh = (const float*)d_in[2];
    const float* b_ih = (const float*)d_in[3];
    const float* b_hh = (const float*)d_in[4];
    const float* W_kr = (const float*)d_in[5];
    const float* b_kr = (const float*)d_in[6];
    const float* w_br = (const float*)d_in[7];
    const float* W_kw = (const float*)d_in[8];
    const float* b_kw = (const float*)d_in[9];
    const float* w_bw = (const float*)d_in[10];
    const float* W_e  = (const float*)d_in[11];
    const float* b_e  = (const float*)d_in[12];
    const float* W_a  = (const float*)d_in[13];
    const float* b_a  = (const float*)d_in[14];
    const float* h0   = (const float*)d_in[15];
    const float* c0   = (const float*)d_in[16];
    const float* r0   = (const float*)d_in[17];
    const float* mem0 = (const float*)d_in[18];
    float* out = (float*)d_out;

    float *p_pre, *p_av;
    cudaGetSymbolAddress((void**)&p_pre, g_pre);
    cudaGetSymbolAddress((void**)&p_av,  g_av);

    cudaFuncSetAttribute(persist, cudaFuncAttributeMaxDynamicSharedMemorySize, SMEM_TOT_BYTES);

    init_all<<<128, 256>>>(h0, r0, W_kw, W_kr, W_e, W_a);                        // 0
    gemm_pre<<<dim3(GATES/GP_TN, (T_STEPS*BATCH)/GP_TM), 256>>>(embs, W_ih, b_ih, b_hh, p_pre); // 1
    pre_a_kernel<<<(T_STEPS*BATCH)/8, 256>>>(embs, b_a, p_av);                   // 2
    persist<<<NCTA, NTHR, SMEM_TOT_BYTES>>>(W_ih, W_hh, c0, mem0,                // 3
                                            b_kr, w_br, b_kw, w_bw, b_e, out);
}